// round 7
// baseline (speedup 1.0000x reference)
#include <cuda_runtime.h>
#include <cstdint>

#define NUM_DENSE 13
#define NUM_SPARSE 26
#define FEAT_NUM 40000
#define FLE 1040013                       // feature length (elements)
#define BATCH 4096
#define NGROUP 6
#define N_GATHER_CTAS 1024                // 4 batch rows per CTA
#define N_WARM_CTAS 512

// Scratch (static device globals — allocation-free).
__device__ float g_sv[(size_t)NGROUP * BATCH * 64];   // partial sv vectors
__device__ float g_sc[(size_t)NGROUP * BATCH];        // partial scalar (w-sum - 0.5*s2)
__device__ float g_sink[N_WARM_CTAS];                 // DCE sink for warm pass

// ---------------------------------------------------------------------------
// Warm: stream V rows k=0..63 over columns [13 + ws0*40000, 13 + ws1*40000)
// with coalesced float4 loads so the band becomes L2-resident at full-line
// efficiency. Sum into acc; conditionally sink so loads can't be eliminated.
// ---------------------------------------------------------------------------
__device__ __forceinline__ void warm_role(const float* __restrict__ V,
                                          int warm_cta, int ws0, int ws1)
{
    const size_t wtid    = (size_t)warm_cta * 256 + threadIdx.x;
    const size_t wstride = (size_t)N_WARM_CTAS * 256;
    const size_t col0 = NUM_DENSE + (size_t)ws0 * FEAT_NUM;
    const size_t colN = NUM_DENSE + (size_t)ws1 * FEAT_NUM;
    const float4* __restrict__ V4 = (const float4*)V;

    float acc = 0.f;
    for (int k = 0; k < 64; k++) {
        size_t base = (size_t)k * FLE;
        size_t a = (base + col0 + 3) & ~(size_t)3;   // absolute 16B-aligned start
        size_t e = base + colN;
        size_t n4 = (e - a) >> 2;
        const float4* __restrict__ p = V4 + (a >> 2);
        for (size_t i = wtid; i < n4; i += wstride) {
            float4 v = __ldg(p + i);
            acc += v.x + v.y + v.z + v.w;
        }
    }
    if (acc == -1.234567e37f) g_sink[warm_cta] = acc;  // never true; keeps loads
}

// ---------------------------------------------------------------------------
// Gather for slot group [gs0, gs1): 4 batch rows per 256-thread CTA; thread
// t (0..63) owns V row k=t. Loads hit the L2-resident band from the warm pass.
// sv is additive over slots -> store partial vector. s2 and first-order w-sum
// are scalar-additive -> block-reduce to one scalar per (group, batch).
// ---------------------------------------------------------------------------
__device__ __forceinline__ void gather_role(const int* __restrict__ sparse,
                                            const float* __restrict__ w,
                                            const float* __restrict__ V,
                                            int g, int gs0, int gs1)
{
    const int tid = threadIdx.x;
    const int sub = tid >> 6;            // which of 4 batch rows
    const int t   = tid & 63;            // k index
    const int b   = blockIdx.x * 4 + sub;
    const int ns  = gs1 - gs0;           // 4 or 5 slots

    __shared__ int   cols[4][8];
    __shared__ float ssum[4][2];

    if (t < ns) {
        int idx = sparse[b * NUM_SPARSE + gs0 + t];
        cols[sub][t] = idx + NUM_DENSE + (gs0 + t) * FEAT_NUM;
    }
    __syncthreads();

    const float* __restrict__ Vrow = V + (size_t)t * FLE;
    float sv = 0.f, s2 = 0.f;
#pragma unroll
    for (int j = 0; j < 5; j++) {
        if (j < ns) {
            float v = __ldg(Vrow + cols[sub][j]);
            sv += v;
            s2 = fmaf(v, v, s2);
        }
    }
    g_sv[((size_t)g * BATCH + b) * 64 + t] = sv;

    float part = -0.5f * s2;
    if (t < ns) part += __ldg(w + cols[sub][t]);

#pragma unroll
    for (int off = 16; off > 0; off >>= 1)
        part += __shfl_down_sync(0xFFFFFFFFu, part, off);
    if ((t & 31) == 0) ssum[sub][t >> 5] = part;
    __syncthreads();
    if (t == 0) g_sc[(size_t)g * BATCH + b] = ssum[sub][0] + ssum[sub][1];
}

// Warm-only kernel (prologue for group 0).
__global__ __launch_bounds__(256) void fm_warm(const float* __restrict__ V,
                                               int ws0, int ws1)
{
    warm_role(V, blockIdx.x, ws0, ws1);
}

// Combined: gather CTAs first (serve group g from L2), warm CTAs after
// (prefetch group g+1). Roles split by blockIdx; per-CTA sync only.
__global__ __launch_bounds__(256) void fm_combo(const int* __restrict__ sparse,
                                                const float* __restrict__ w,
                                                const float* __restrict__ V,
                                                int g, int gs0, int gs1,
                                                int ws0, int ws1)
{
    if (blockIdx.x < N_GATHER_CTAS) {
        gather_role(sparse, w, V, g, gs0, gs1);
    } else {
        if (ws0 >= ws1) return;          // epilogue launch: no warm work
        warm_role(V, blockIdx.x - N_GATHER_CTAS, ws0, ws1);
    }
}

// Final: combine partials + dense contributions, reduce, write out.
__global__ __launch_bounds__(64) void fm_final(const float* __restrict__ dense,
                                               const float* __restrict__ w0,
                                               const float* __restrict__ w,
                                               const float* __restrict__ V,
                                               float* __restrict__ out)
{
    const int b = blockIdx.x;
    const int t = threadIdx.x;
    __shared__ float xd[NUM_DENSE];
    __shared__ float ssum[2];

    if (t < NUM_DENSE) xd[t] = dense[b * NUM_DENSE + t];
    __syncthreads();

    float sv = 0.f;
#pragma unroll
    for (int g = 0; g < NGROUP; g++)
        sv += g_sv[((size_t)g * BATCH + b) * 64 + t];

    float s2d = 0.f;
    const float* __restrict__ Vrow = V + (size_t)t * FLE;
#pragma unroll
    for (int d = 0; d < NUM_DENSE; d++) {
        float xv = xd[d] * __ldg(Vrow + d);     // L2-hot: same cols for all b
        sv += xv;
        s2d = fmaf(xv, xv, s2d);
    }

    float part = 0.5f * fmaf(sv, sv, -s2d);
    if (t < NUM_DENSE) part += xd[t] * __ldg(w + t);

#pragma unroll
    for (int off = 16; off > 0; off >>= 1)
        part += __shfl_down_sync(0xFFFFFFFFu, part, off);
    if ((t & 31) == 0) ssum[t >> 5] = part;
    __syncthreads();
    if (t == 0) {
        float r = w0[0] + ssum[0] + ssum[1];
#pragma unroll
        for (int g = 0; g < NGROUP; g++)
            r += g_sc[(size_t)g * BATCH + b];
        out[b] = r;
    }
}

extern "C" void kernel_launch(void* const* d_in, const int* in_sizes, int n_in,
                              void* d_out, int out_size)
{
    const float* dense  = (const float*)d_in[0];      // [4096,13] f32
    const int*   sparse = (const int*)d_in[1];        // [4096,26] int32
    const float* w0     = (const float*)d_in[2];      // [1]
    const float* w      = (const float*)d_in[3];      // [1040013]
    const float* V      = (const float*)d_in[4];      // [64,1040013]
    float*       out    = (float*)d_out;              // [4096]

    // Slot group boundaries: sizes {5,5,4,4,4,4}; bands 51/51/41/41/41/41 MB.
    static const int GS[NGROUP + 1] = {0, 5, 10, 14, 18, 22, 26};

    // Prologue: warm group 0's band into L2.
    fm_warm<<<N_WARM_CTAS, 256>>>(V, GS[0], GS[1]);

    // Pipeline: gather group g (L2 hits) overlapped with warm of group g+1.
    for (int g = 0; g < NGROUP; g++) {
        int ws0 = (g + 1 < NGROUP) ? GS[g + 1] : 0;
        int ws1 = (g + 1 < NGROUP) ? GS[g + 2] : 0;
        fm_combo<<<N_GATHER_CTAS + N_WARM_CTAS, 256>>>(
            sparse, w, V, g, GS[g], GS[g + 1], ws0, ws1);
    }

    fm_final<<<BATCH, 64>>>(dense, w0, w, V, out);
}

// round 9
// speedup vs baseline: 4.3339x; 4.3339x over previous
#include <cuda_runtime.h>
#include <cstdint>

#define NUM_DENSE 13
#define NUM_SPARSE 26
#define FEAT_NUM 40000
#define FLE 1040013                       // feature length (elements)
#define BATCH 4096
#define NGROUP 6
#define CTAS_PER_GROUP 1024               // 4 batch rows per 256-thread CTA

// Slot-group boundaries {5,5,4,4,4,4}: bands of 51/51/41/41/41/41 MB,
// each < L2 (126 MB) so a phase's working set stays resident.
__constant__ int c_GS[NGROUP + 1] = {0, 5, 10, 14, 18, 22, 26};

// Static scratch (allocation-free): partial results per (group, batch).
__device__ float g_sv[(size_t)NGROUP * BATCH * 64];   // partial sv vectors
__device__ float g_sc[(size_t)NGROUP * BATCH];        // w-sum - 0.5*s2 partials

// ---------------------------------------------------------------------------
// Phased gather, ONE kernel: blockIdx.x = g * CTAS_PER_GROUP + cta_in_group.
// CTAs dispatch in bid order and one group is ~one full wave (8192 warps vs
// 9472 chip capacity), so groups execute in temporal phases and each group's
// V-band is fetched from DRAM once and then served from L2 (~3.3 touches per
// 128B line on average).
// Thread layout: sub = tid/64 selects one of 4 batch rows, t = tid%64 = k.
// ---------------------------------------------------------------------------
__global__ __launch_bounds__(256) void fm_gather(const int* __restrict__ sparse,
                                                 const float* __restrict__ w,
                                                 const float* __restrict__ V)
{
    const int g   = blockIdx.x >> 10;           // group index 0..5
    const int cig = blockIdx.x & 1023;          // CTA within group
    const int tid = threadIdx.x;
    const int sub = tid >> 6;                   // 0..3 batch sub-row
    const int t   = tid & 63;                   // k index
    const int b   = cig * 4 + sub;
    const int gs0 = c_GS[g];
    const int ns  = c_GS[g + 1] - gs0;          // 4 or 5 slots

    __shared__ int   cols[4][8];
    __shared__ float ssum[4][2];

    if (t < ns) {
        int idx = sparse[b * NUM_SPARSE + gs0 + t];
        cols[sub][t] = idx + NUM_DENSE + (gs0 + t) * FEAT_NUM;
    }
    __syncthreads();

    const float* __restrict__ Vrow = V + (size_t)t * FLE;

    // Front-batch the (up to 5) gathers for MLP.
    float vv[5];
#pragma unroll
    for (int j = 0; j < 5; j++)
        vv[j] = (j < ns) ? __ldg(Vrow + cols[sub][j]) : 0.f;

    float sv = 0.f, s2 = 0.f;
#pragma unroll
    for (int j = 0; j < 5; j++) {
        sv += vv[j];
        s2 = fmaf(vv[j], vv[j], s2);
    }
    g_sv[((size_t)g * BATCH + b) * 64 + t] = sv;

    // First-order term (w is 4.2 MB -> L2-hot) + 0.5*s2 partial.
    float part = -0.5f * s2;
    if (t < ns) part += __ldg(w + cols[sub][t]);

#pragma unroll
    for (int off = 16; off > 0; off >>= 1)
        part += __shfl_down_sync(0xFFFFFFFFu, part, off);
    if ((t & 31) == 0) ssum[sub][t >> 5] = part;
    __syncthreads();
    if (t == 0) g_sc[(size_t)g * BATCH + b] = ssum[sub][0] + ssum[sub][1];
}

// ---------------------------------------------------------------------------
// Final: sum partial sv vectors, add dense contributions, square-reduce.
// 4 batch rows per 256-thread CTA.
// ---------------------------------------------------------------------------
__global__ __launch_bounds__(256) void fm_final(const float* __restrict__ dense,
                                                const float* __restrict__ w0,
                                                const float* __restrict__ w,
                                                const float* __restrict__ V,
                                                float* __restrict__ out)
{
    const int tid = threadIdx.x;
    const int sub = tid >> 6;
    const int t   = tid & 63;
    const int b   = blockIdx.x * 4 + sub;

    __shared__ float xd[4][NUM_DENSE];
    __shared__ float ssum[4][2];

    if (t < NUM_DENSE) xd[sub][t] = dense[b * NUM_DENSE + t];
    __syncthreads();

    float sv = 0.f;
#pragma unroll
    for (int g = 0; g < NGROUP; g++)
        sv += g_sv[((size_t)g * BATCH + b) * 64 + t];

    float s2d = 0.f;
    const float* __restrict__ Vrow = V + (size_t)t * FLE;
#pragma unroll
    for (int d = 0; d < NUM_DENSE; d++) {
        float xv = xd[sub][d] * __ldg(Vrow + d);   // same 13 cols for all b: L2-hot
        sv += xv;
        s2d = fmaf(xv, xv, s2d);
    }

    float part = 0.5f * fmaf(sv, sv, -s2d);
    if (t < NUM_DENSE) part += xd[sub][t] * __ldg(w + t);

#pragma unroll
    for (int off = 16; off > 0; off >>= 1)
        part += __shfl_down_sync(0xFFFFFFFFu, part, off);
    if ((t & 31) == 0) ssum[sub][t >> 5] = part;
    __syncthreads();
    if (t == 0) {
        float r = w0[0] + ssum[sub][0] + ssum[sub][1];
#pragma unroll
        for (int g = 0; g < NGROUP; g++)
            r += g_sc[(size_t)g * BATCH + b];
        out[b] = r;
    }
}

extern "C" void kernel_launch(void* const* d_in, const int* in_sizes, int n_in,
                              void* d_out, int out_size)
{
    const float* dense  = (const float*)d_in[0];      // [4096,13] f32
    const int*   sparse = (const int*)d_in[1];        // [4096,26] int32
    const float* w0     = (const float*)d_in[2];      // [1]
    const float* w      = (const float*)d_in[3];      // [1040013]
    const float* V      = (const float*)d_in[4];      // [64,1040013]
    float*       out    = (float*)d_out;              // [4096]

    fm_gather<<<NGROUP * CTAS_PER_GROUP, 256>>>(sparse, w, V);
    fm_final<<<BATCH / 4, 256>>>(dense, w0, w, V, out);
}